// round 6
// baseline (speedup 1.0000x reference)
#include <cuda_runtime.h>
#include <cuda_bf16.h>
#include <cstdint>
#include <math.h>

// Problem sizes (fixed)
#define B_   64
#define S_   2048
#define M_   1024   // K of scores GEMM (memory feature dim)
#define D_   1024   // N of scores GEMM (decoder feature dim)

// ---------------------------------------------------------------------------
// Scratch (no allocations allowed)
// ---------------------------------------------------------------------------
__device__ float g_scores[B_ * S_];          // 512 KB
__device__ float g_decf[B_ * D_];            // 256 KB
__device__ float g_Wt[D_ * M_];              // 4 MB: W_mem transposed [d][k'], K fully permuted

// ---------------------------------------------------------------------------
// Helpers
// ---------------------------------------------------------------------------
__device__ __forceinline__ uint32_t smem_u32(const void* p) {
    uint32_t a;
    asm("{ .reg .u64 t; cvta.to.shared.u64 t, %1; cvt.u32.u64 %0, t; }"
        : "=r"(a) : "l"(p));
    return a;
}

__device__ __forceinline__ void cp_async16(uint32_t dst, const void* src) {
    asm volatile("cp.async.cg.shared.global [%0], [%1], 16;"
                 :: "r"(dst), "l"(src));
}
#define CP_ASYNC_COMMIT() asm volatile("cp.async.commit_group;" ::: "memory")
#define CP_ASYNC_WAIT(n)  asm volatile("cp.async.wait_group %0;" :: "n"(n) : "memory")

// mma.sync m16n8k8 tf32 (legacy tensor path, valid on compute_103)
__device__ __forceinline__ void mma_tf32(float* c,
                                         float a0, float a1, float a2, float a3,
                                         float b0, float b1) {
    asm volatile(
        "mma.sync.aligned.m16n8k8.row.col.f32.tf32.tf32.f32 "
        "{%0,%1,%2,%3}, {%4,%5,%6,%7}, {%8,%9}, {%0,%1,%2,%3};"
        : "+f"(c[0]), "+f"(c[1]), "+f"(c[2]), "+f"(c[3])
        : "r"(__float_as_uint(a0)), "r"(__float_as_uint(a1)),
          "r"(__float_as_uint(a2)), "r"(__float_as_uint(a3)),
          "r"(__float_as_uint(b0)), "r"(__float_as_uint(b1)));
}

// ---------------------------------------------------------------------------
// Kernel: zero scores accumulator + ctx output region
// ---------------------------------------------------------------------------
__global__ __launch_bounds__(512) void zero_kernel(float* __restrict__ ctx) {
    int i = blockIdx.x * 512 + threadIdx.x;
    if (i < B_ * S_) g_scores[i] = 0.0f;
    if (i < B_ * M_) ctx[i] = 0.0f;
}

// ---------------------------------------------------------------------------
// Kernel: transpose W_mem [k][d] -> g_Wt [d][k'], K fully permuted within
// each 8... 32-block:  pos(k) = (k&3)*8 + ((k>>3)&3)*2 + ((k>>2)&1)
// so the fragment pairs for (q, ks) and (q, ks+1) are 4 consecutive floats.
// ---------------------------------------------------------------------------
__global__ __launch_bounds__(256) void transpose_kernel(const float* __restrict__ W) {
    __shared__ float t[32][33];
    int dblk = blockIdx.x * 32;
    int kblk = blockIdx.y * 32;
    int tx = threadIdx.x & 31;
    int ty = threadIdx.x >> 5;     // 0..7
    #pragma unroll
    for (int j = 0; j < 32; j += 8)
        t[ty + j][tx] = W[(size_t)(kblk + ty + j) * D_ + dblk + tx];
    __syncthreads();
    int kp = (tx & 3) * 8 + ((tx >> 3) & 3) * 2 + ((tx >> 2) & 1);
    #pragma unroll
    for (int j = 0; j < 32; j += 8)
        g_Wt[(size_t)(dblk + ty + j) * M_ + kblk + kp] = t[tx][ty + j];
}

// ---------------------------------------------------------------------------
// Kernel: dec_feat[b][d] = decoder_state[b] @ W_dec
// ---------------------------------------------------------------------------
__global__ __launch_bounds__(256) void dec_feat_kernel(
    const float* __restrict__ decoder_state,
    const float* __restrict__ W_dec)
{
    __shared__ float ds[4][M_];
    int tid = threadIdx.x;
    int d   = blockIdx.x * 256 + tid;
    int bg  = blockIdx.y * 4;

    for (int i = tid; i < 4 * M_; i += 256)
        ds[i >> 10][i & (M_ - 1)] = decoder_state[(bg + (i >> 10)) * M_ + (i & (M_ - 1))];
    __syncthreads();

    float a0 = 0.f, a1 = 0.f, a2 = 0.f, a3 = 0.f;
    for (int m = 0; m < M_; m++) {
        float w = W_dec[(size_t)m * D_ + d];
        a0 += ds[0][m] * w; a1 += ds[1][m] * w;
        a2 += ds[2][m] * w; a3 += ds[3][m] * w;
    }
    g_decf[(bg + 0) * D_ + d] = a0;
    g_decf[(bg + 1) * D_ + d] = a1;
    g_decf[(bg + 2) * D_ + d] = a2;
    g_decf[(bg + 3) * D_ + d] = a3;
}

// ---------------------------------------------------------------------------
// Scores GEMM: C[s][d] = sum_k mem[b][s][k] * W_mem[k][d], fused
//   score[s] += sum_d Wv[d] * tanh(C[s][d] + decf[b][d])
//
// mma.sync m16n8k8 tf32, CTA tile 128x128x32, 8 warps (4x2), warp tile 32x64.
// 3-stage cp.async pipeline.
// A smem: [s][k] stride 32, XOR chunk swizzle (c ^= row&7) -> scalar LDS
//         conflict-free.
// B smem: [d][k'] stride 36 (fully permuted K) -> LDS.128 gives fragments
//         for 2 consecutive ks steps; conflict-free per quarter-warp.
// ---------------------------------------------------------------------------
#define A_FLOATS (128 * 32)
#define B_STRIDE 36
#define STAGE_FLOATS (A_FLOATS + 128 * B_STRIDE)    // 8704 floats (34816 B)
#define STAGES 3
#define SM_BYTES (STAGES * STAGE_FLOATS * 4)        // 104448

extern __shared__ float smem[];

__global__ __launch_bounds__(256, 2)
void scores_mma_kernel(const float* __restrict__ memory_bank,
                       const float* __restrict__ W_v)
{
    int tid  = threadIdx.x;
    int wid  = tid >> 5;
    int lane = tid & 31;
    int grp  = lane >> 2;         // 0..7
    int q    = lane & 3;          // 0..3
    int warp_m = wid & 3;         // 4 warps along s
    int warp_n = wid >> 2;        // 2 warps along d

    int d_base = blockIdx.x * 128;     // d fastest-varying -> A reuse in L2
    int s_base = blockIdx.y * 128;
    int b      = blockIdx.z;

    const float* Abase = memory_bank + ((size_t)b * S_ + s_base) * M_;
    const float* Bbase = g_Wt + (size_t)d_base * M_;

    uint32_t smem_base = smem_u32(smem);

    int lrow = tid >> 3;          // 0..31 (combined with +32*i)
    int lc   = tid & 7;           // 16B chunk within row
    int lcA  = lc ^ (lrow & 7);   // XOR-swizzled A chunk

    auto load_stage = [&](int kt, int st) {
        int k0 = kt * 32;
        uint32_t dstA = smem_base + (uint32_t)(st * STAGE_FLOATS) * 4;
        uint32_t dstB = dstA + A_FLOATS * 4;
        #pragma unroll
        for (int i = 0; i < 4; i++) {
            int row = lrow + i * 32;
            cp_async16(dstA + (uint32_t)(row * 32 + lcA * 4) * 4,
                       Abase + (size_t)row * M_ + k0 + lc * 4);
        }
        #pragma unroll
        for (int i = 0; i < 4; i++) {
            int row = lrow + i * 32;
            cp_async16(dstB + (uint32_t)(row * B_STRIDE + lc * 4) * 4,
                       Bbase + (size_t)row * M_ + k0 + lc * 4);
        }
        CP_ASYNC_COMMIT();
    };

    float acc[2][8][4];
    #pragma unroll
    for (int mt = 0; mt < 2; mt++)
        #pragma unroll
        for (int nt = 0; nt < 8; nt++)
            #pragma unroll
            for (int i = 0; i < 4; i++)
                acc[mt][nt][i] = 0.0f;

    load_stage(0, 0);
    load_stage(1, 1);

    int rowA0 = warp_m * 32 + grp;
    int rowB0 = warp_n * 64 + grp;

    for (int kt = 0; kt < 32; kt++) {
        if (kt == 31) { CP_ASYNC_WAIT(0); } else { CP_ASYNC_WAIT(1); }
        __syncthreads();

        if (kt + 2 < 32) load_stage(kt + 2, (kt + 2) % 3);

        const float* stA = smem + (kt % 3) * STAGE_FLOATS;
        const float* stB = stA + A_FLOATS;
        const float* bb  = stB + (size_t)rowB0 * B_STRIDE + q * 8;

        #pragma unroll
        for (int ksp = 0; ksp < 2; ksp++) {       // each covers 2 ks steps
            float4 bf[8];
            #pragma unroll
            for (int nt = 0; nt < 8; nt++)
                bf[nt] = *reinterpret_cast<const float4*>(
                    bb + nt * 8 * B_STRIDE + ksp * 4);

            #pragma unroll
            for (int kh = 0; kh < 2; kh++) {
                int ks = 2 * ksp + kh;
                int c0 = ((2 * ks) ^ grp) * 4 + q;       // k = ks*8+q
                int c1 = ((2 * ks + 1) ^ grp) * 4 + q;   // k = ks*8+q+4
                #pragma unroll
                for (int mt = 0; mt < 2; mt++) {
                    int r0 = rowA0 + mt * 16;
                    float a0 = stA[r0 * 32 + c0];
                    float a1 = stA[(r0 + 8) * 32 + c0];
                    float a2 = stA[r0 * 32 + c1];
                    float a3 = stA[(r0 + 8) * 32 + c1];
                    #pragma unroll
                    for (int nt = 0; nt < 8; nt++) {
                        float b0v = kh ? bf[nt].z : bf[nt].x;
                        float b1v = kh ? bf[nt].w : bf[nt].y;
                        mma_tf32(acc[mt][nt], a0, a1, a2, a3, b0v, b1v);
                    }
                }
            }
        }
    }

    // ---- epilogue: score[s] += sum_d Wv[d]*tanh(C + decf[d]) ----
    __syncthreads();
    float* s_df = smem;           // [128]
    float* s_wv = smem + 128;     // [128]
    if (tid < 128)       s_df[tid] = g_decf[b * D_ + d_base + tid];
    else                 s_wv[tid - 128] = W_v[d_base + tid - 128];
    __syncthreads();

    float part[4] = {0.f, 0.f, 0.f, 0.f};
    #pragma unroll
    for (int mt = 0; mt < 2; mt++) {
        #pragma unroll
        for (int nt = 0; nt < 8; nt++) {
            int col0 = warp_n * 64 + nt * 8 + 2 * q;
            float wv0 = s_wv[col0], wv1 = s_wv[col0 + 1];
            float df0 = s_df[col0], df1 = s_df[col0 + 1];
            part[2 * mt]     += wv0 * tanhf(acc[mt][nt][0] + df0)
                              + wv1 * tanhf(acc[mt][nt][1] + df1);
            part[2 * mt + 1] += wv0 * tanhf(acc[mt][nt][2] + df0)
                              + wv1 * tanhf(acc[mt][nt][3] + df1);
        }
    }
    #pragma unroll
    for (int i = 0; i < 4; i++) {
        part[i] += __shfl_xor_sync(0xFFFFFFFFu, part[i], 1);
        part[i] += __shfl_xor_sync(0xFFFFFFFFu, part[i], 2);
    }
    if (q == 0) {
        int rbase = b * S_ + s_base + warp_m * 32 + grp;
        atomicAdd(&g_scores[rbase],      part[0]);
        atomicAdd(&g_scores[rbase + 8],  part[1]);
        atomicAdd(&g_scores[rbase + 16], part[2]);
        atomicAdd(&g_scores[rbase + 24], part[3]);
    }
}

// ---------------------------------------------------------------------------
// Softmax over S per batch (masked)
// ---------------------------------------------------------------------------
__global__ __launch_bounds__(256) void softmax_kernel(
    const int* __restrict__ src_mask,
    float* __restrict__ attn_out)
{
    __shared__ float red[8];
    int b = blockIdx.x, tid = threadIdx.x;
    int lane = tid & 31, wid = tid >> 5;

    float v[8];
    float mx = -3.4e38f;
    #pragma unroll
    for (int j = 0; j < 8; j++) {
        int idx = tid + j * 256;
        float s = g_scores[b * S_ + idx];
        if (src_mask[b * S_ + idx] == 0) s = -3.4e38f;
        v[j] = s;
        mx = fmaxf(mx, s);
    }
    #pragma unroll
    for (int off = 16; off > 0; off >>= 1)
        mx = fmaxf(mx, __shfl_xor_sync(0xFFFFFFFFu, mx, off));
    if (lane == 0) red[wid] = mx;
    __syncthreads();
    if (tid == 0) {
        float m2 = red[0];
        #pragma unroll
        for (int w = 1; w < 8; w++) m2 = fmaxf(m2, red[w]);
        red[0] = m2;
    }
    __syncthreads();
    mx = red[0];
    __syncthreads();

    float e[8];
    float sum = 0.0f;
    #pragma unroll
    for (int j = 0; j < 8; j++) {
        e[j] = __expf(v[j] - mx);
        sum += e[j];
    }
    #pragma unroll
    for (int off = 16; off > 0; off >>= 1)
        sum += __shfl_xor_sync(0xFFFFFFFFu, sum, off);
    if (lane == 0) red[wid] = sum;
    __syncthreads();
    if (tid == 0) {
        float s2 = 0.0f;
        #pragma unroll
        for (int w = 0; w < 8; w++) s2 += red[w];
        red[0] = s2;
    }
    __syncthreads();
    float inv = 1.0f / red[0];

    #pragma unroll
    for (int j = 0; j < 8; j++)
        attn_out[b * S_ + tid + j * 256] = e[j] * inv;
}

// ---------------------------------------------------------------------------
// context[b][m] += sum_{s in chunk} attn[b][s] * mem[b][s][m]
// grid (4 m-chunks, 4 s-chunks, 64 b) = 1024 CTAs; atomicAdd partials.
// ---------------------------------------------------------------------------
#define SCHUNK 512
__global__ __launch_bounds__(256) void context_kernel(
    const float* __restrict__ attn,
    const float* __restrict__ memory_bank,
    float* __restrict__ ctx_out)
{
    __shared__ float sa[SCHUNK];
    int tid = threadIdx.x;
    int b   = blockIdx.z;
    int s0  = blockIdx.y * SCHUNK;
    int m0  = blockIdx.x * 256;

    #pragma unroll
    for (int j = 0; j < SCHUNK / 256; j++)
        sa[tid + j * 256] = attn[b * S_ + s0 + tid + j * 256];
    __syncthreads();

    const float* base = memory_bank + ((size_t)b * S_ + s0) * M_ + m0 + tid;
    float a0 = 0.f, a1 = 0.f, a2 = 0.f, a3 = 0.f;
    for (int s = 0; s < SCHUNK; s += 4) {
        a0 += sa[s + 0] * base[(size_t)(s + 0) * M_];
        a1 += sa[s + 1] * base[(size_t)(s + 1) * M_];
        a2 += sa[s + 2] * base[(size_t)(s + 2) * M_];
        a3 += sa[s + 3] * base[(size_t)(s + 3) * M_];
    }
    atomicAdd(&ctx_out[b * M_ + m0 + tid], (a0 + a1) + (a2 + a3));
}

// ---------------------------------------------------------------------------
// Launch
// ---------------------------------------------------------------------------
extern "C" void kernel_launch(void* const* d_in, const int* in_sizes, int n_in,
                              void* d_out, int out_size)
{
    const float* decoder_state = (const float*)d_in[0];
    const float* memory_bank   = (const float*)d_in[1];
    const int*   src_mask      = (const int*)  d_in[2];
    const float* W_v           = (const float*)d_in[3];
    const float* W_dec         = (const float*)d_in[4];
    const float* W_mem         = (const float*)d_in[5];

    float* out  = (float*)d_out;
    float* ctx  = out;                 // [64, 1024]
    float* attn = out + B_ * M_;       // [64, 2048]

    cudaFuncSetAttribute(scores_mma_kernel,
                         cudaFuncAttributeMaxDynamicSharedMemorySize, SM_BYTES);

    zero_kernel<<<B_ * S_ / 512, 512>>>(ctx);
    transpose_kernel<<<dim3(32, 32), 256>>>(W_mem);
    dec_feat_kernel<<<dim3(D_ / 256, B_ / 4), 256>>>(decoder_state, W_dec);
    scores_mma_kernel<<<dim3(D_ / 128, S_ / 128, B_), 256, SM_BYTES>>>(memory_bank, W_v);
    softmax_kernel<<<B_, 256>>>(src_mask, attn);
    context_kernel<<<dim3(M_ / 256, S_ / SCHUNK, B_), 256>>>(attn, memory_bank, ctx);
}

// round 7
// speedup vs baseline: 1.1067x; 1.1067x over previous
#include <cuda_runtime.h>
#include <cuda_bf16.h>
#include <cstdint>
#include <math.h>

// Problem sizes (fixed)
#define B_   64
#define S_   2048
#define M_   1024   // K of scores GEMM (memory feature dim)
#define D_   1024   // N of scores GEMM (decoder feature dim)

// ---------------------------------------------------------------------------
// Scratch (no allocations allowed)
// ---------------------------------------------------------------------------
__device__ float g_scores[B_ * S_];          // 512 KB
__device__ float g_decf[B_ * D_];            // 256 KB
__device__ float g_Wt[D_ * M_];              // 4 MB: W_mem transposed [d][k'], K pair-permuted

// ---------------------------------------------------------------------------
// Helpers
// ---------------------------------------------------------------------------
__device__ __forceinline__ uint32_t smem_u32(const void* p) {
    uint32_t a;
    asm("{ .reg .u64 t; cvta.to.shared.u64 t, %1; cvt.u32.u64 %0, t; }"
        : "=r"(a) : "l"(p));
    return a;
}

__device__ __forceinline__ void cp_async16(uint32_t dst, const void* src) {
    asm volatile("cp.async.cg.shared.global [%0], [%1], 16;"
                 :: "r"(dst), "l"(src));
}
#define CP_ASYNC_COMMIT() asm volatile("cp.async.commit_group;" ::: "memory")
#define CP_ASYNC_WAIT(n)  asm volatile("cp.async.wait_group %0;" :: "n"(n) : "memory")

// mma.sync m16n8k8 tf32 (legacy tensor path, valid on compute_103)
__device__ __forceinline__ void mma_tf32(float* c,
                                         float a0, float a1, float a2, float a3,
                                         float b0, float b1) {
    asm volatile(
        "mma.sync.aligned.m16n8k8.row.col.f32.tf32.tf32.f32 "
        "{%0,%1,%2,%3}, {%4,%5,%6,%7}, {%8,%9}, {%0,%1,%2,%3};"
        : "+f"(c[0]), "+f"(c[1]), "+f"(c[2]), "+f"(c[3])
        : "r"(__float_as_uint(a0)), "r"(__float_as_uint(a1)),
          "r"(__float_as_uint(a2)), "r"(__float_as_uint(a3)),
          "r"(__float_as_uint(b0)), "r"(__float_as_uint(b1)));
}

// ---------------------------------------------------------------------------
// Kernel: zero scores accumulator + ctx output region
// ---------------------------------------------------------------------------
__global__ __launch_bounds__(512) void zero_kernel(float* __restrict__ ctx) {
    int i = blockIdx.x * 512 + threadIdx.x;
    if (i < B_ * S_) g_scores[i] = 0.0f;
    if (i < B_ * M_) ctx[i] = 0.0f;
}

// ---------------------------------------------------------------------------
// Kernel: transpose W_mem [k][d] -> g_Wt [d][k'], with K pair-permutation
// within each 8-block so that (q, q+4) land at (2q, 2q+1):
//   p(k) = (k & ~7) | ((k&3)<<1) | ((k>>2)&1)
// ---------------------------------------------------------------------------
__global__ __launch_bounds__(256) void transpose_kernel(const float* __restrict__ W) {
    __shared__ float t[32][33];
    int dblk = blockIdx.x * 32;
    int kblk = blockIdx.y * 32;
    int tx = threadIdx.x & 31;
    int ty = threadIdx.x >> 5;     // 0..7
    #pragma unroll
    for (int j = 0; j < 32; j += 8)
        t[ty + j][tx] = W[(size_t)(kblk + ty + j) * D_ + dblk + tx];
    __syncthreads();
    int kp = (tx & ~7) | ((tx & 3) << 1) | ((tx >> 2) & 1);   // pair permutation
    #pragma unroll
    for (int j = 0; j < 32; j += 8)
        g_Wt[(size_t)(dblk + ty + j) * M_ + kblk + kp] = t[tx][ty + j];
}

// ---------------------------------------------------------------------------
// Kernel: dec_feat[b][d] = decoder_state[b] @ W_dec
// ---------------------------------------------------------------------------
__global__ __launch_bounds__(256) void dec_feat_kernel(
    const float* __restrict__ decoder_state,
    const float* __restrict__ W_dec)
{
    __shared__ float ds[4][M_];
    int tid = threadIdx.x;
    int d   = blockIdx.x * 256 + tid;
    int bg  = blockIdx.y * 4;

    for (int i = tid; i < 4 * M_; i += 256)
        ds[i >> 10][i & (M_ - 1)] = decoder_state[(bg + (i >> 10)) * M_ + (i & (M_ - 1))];
    __syncthreads();

    float a0 = 0.f, a1 = 0.f, a2 = 0.f, a3 = 0.f;
    for (int m = 0; m < M_; m++) {
        float w = W_dec[(size_t)m * D_ + d];
        a0 += ds[0][m] * w; a1 += ds[1][m] * w;
        a2 += ds[2][m] * w; a3 += ds[3][m] * w;
    }
    g_decf[(bg + 0) * D_ + d] = a0;
    g_decf[(bg + 1) * D_ + d] = a1;
    g_decf[(bg + 2) * D_ + d] = a2;
    g_decf[(bg + 3) * D_ + d] = a3;
}

// ---------------------------------------------------------------------------
// Scores GEMM: C[s][d] = sum_k mem[b][s][k] * W_mem[k][d], fused
//   score[s] += sum_d Wv[d] * tanh(C[s][d] + decf[b][d])
//
// mma.sync m16n8k8 tf32, CTA tile 128x128x32, 8 warps (4x2), warp tile 32x64.
// 3-stage cp.async pipeline.  (R5 configuration — measured best)
// A smem: [s][k] stride 32, XOR chunk swizzle (c ^= row&7) -> scalar LDS
//         conflict-free.
// B smem: [d][k'] stride 40 (pair-permuted K) -> LDS.64 fragments,
//         conflict-free (stride 40 = 8 mod 32 banks).
// ---------------------------------------------------------------------------
#define A_FLOATS (128 * 32)
#define B_STRIDE 40
#define STAGE_FLOATS (A_FLOATS + 128 * B_STRIDE)    // 9216 floats (36864 B)
#define STAGES 3
#define SM_BYTES (STAGES * STAGE_FLOATS * 4)        // 110592

extern __shared__ float smem[];

__global__ __launch_bounds__(256, 2)
void scores_mma_kernel(const float* __restrict__ memory_bank,
                       const float* __restrict__ W_v)
{
    int tid  = threadIdx.x;
    int wid  = tid >> 5;
    int lane = tid & 31;
    int grp  = lane >> 2;         // 0..7
    int q    = lane & 3;          // 0..3
    int warp_m = wid & 3;         // 4 warps along s
    int warp_n = wid >> 2;        // 2 warps along d

    int d_base = blockIdx.x * 128;     // d fastest-varying -> A reuse in L2
    int s_base = blockIdx.y * 128;
    int b      = blockIdx.z;

    const float* Abase = memory_bank + ((size_t)b * S_ + s_base) * M_;
    const float* Bbase = g_Wt + (size_t)d_base * M_;

    uint32_t smem_base = smem_u32(smem);

    int lrow = tid >> 3;          // 0..31 (combined with +32*i)
    int lc   = tid & 7;           // 16B chunk within row
    int lcA  = lc ^ (lrow & 7);   // XOR-swizzled A chunk

    auto load_stage = [&](int kt, int st) {
        int k0 = kt * 32;
        uint32_t dstA = smem_base + (uint32_t)(st * STAGE_FLOATS) * 4;
        uint32_t dstB = dstA + A_FLOATS * 4;
        #pragma unroll
        for (int i = 0; i < 4; i++) {
            int row = lrow + i * 32;
            cp_async16(dstA + (uint32_t)(row * 32 + lcA * 4) * 4,
                       Abase + (size_t)row * M_ + k0 + lc * 4);
        }
        #pragma unroll
        for (int i = 0; i < 4; i++) {
            int row = lrow + i * 32;
            cp_async16(dstB + (uint32_t)(row * B_STRIDE + lc * 4) * 4,
                       Bbase + (size_t)row * M_ + k0 + lc * 4);
        }
        CP_ASYNC_COMMIT();
    };

    float acc[2][8][4];
    #pragma unroll
    for (int mt = 0; mt < 2; mt++)
        #pragma unroll
        for (int nt = 0; nt < 8; nt++)
            #pragma unroll
            for (int i = 0; i < 4; i++)
                acc[mt][nt][i] = 0.0f;

    load_stage(0, 0);
    load_stage(1, 1);

    int rowA0 = warp_m * 32 + grp;
    int rowB0 = warp_n * 64 + grp;

    for (int kt = 0; kt < 32; kt++) {
        if (kt == 31) { CP_ASYNC_WAIT(0); } else { CP_ASYNC_WAIT(1); }
        __syncthreads();

        if (kt + 2 < 32) load_stage(kt + 2, (kt + 2) % 3);

        const float* stA = smem + (kt % 3) * STAGE_FLOATS;
        const float* stB = stA + A_FLOATS;
        const float* bb  = stB + (size_t)rowB0 * B_STRIDE + 2 * q;

        #pragma unroll
        for (int ks = 0; ks < 4; ks++) {
            // B fragments: one LDS.64 each (pair-permuted K)
            float2 bf[8];
            #pragma unroll
            for (int nt = 0; nt < 8; nt++)
                bf[nt] = *reinterpret_cast<const float2*>(
                    bb + nt * 8 * B_STRIDE + ks * 8);

            int c0 = ((2 * ks) ^ grp) * 4 + q;       // k = ks*8+q   (swizzled)
            int c1 = ((2 * ks + 1) ^ grp) * 4 + q;   // k = ks*8+q+4 (swizzled)
            #pragma unroll
            for (int mt = 0; mt < 2; mt++) {
                int r0 = rowA0 + mt * 16;
                float a0 = stA[r0 * 32 + c0];
                float a1 = stA[(r0 + 8) * 32 + c0];
                float a2 = stA[r0 * 32 + c1];
                float a3 = stA[(r0 + 8) * 32 + c1];
                #pragma unroll
                for (int nt = 0; nt < 8; nt++)
                    mma_tf32(acc[mt][nt], a0, a1, a2, a3, bf[nt].x, bf[nt].y);
            }
        }
    }

    // ---- epilogue: score[s] += sum_d Wv[d]*tanh(C + decf[d]) ----
    __syncthreads();
    float* s_df = smem;           // [128]
    float* s_wv = smem + 128;     // [128]
    if (tid < 128)       s_df[tid] = g_decf[b * D_ + d_base + tid];
    else                 s_wv[tid - 128] = W_v[d_base + tid - 128];
    __syncthreads();

    float part[4] = {0.f, 0.f, 0.f, 0.f};
    #pragma unroll
    for (int mt = 0; mt < 2; mt++) {
        #pragma unroll
        for (int nt = 0; nt < 8; nt++) {
            int col0 = warp_n * 64 + nt * 8 + 2 * q;
            float wv0 = s_wv[col0], wv1 = s_wv[col0 + 1];
            float df0 = s_df[col0], df1 = s_df[col0 + 1];
            part[2 * mt]     += wv0 * tanhf(acc[mt][nt][0] + df0)
                              + wv1 * tanhf(acc[mt][nt][1] + df1);
            part[2 * mt + 1] += wv0 * tanhf(acc[mt][nt][2] + df0)
                              + wv1 * tanhf(acc[mt][nt][3] + df1);
        }
    }
    #pragma unroll
    for (int i = 0; i < 4; i++) {
        part[i] += __shfl_xor_sync(0xFFFFFFFFu, part[i], 1);
        part[i] += __shfl_xor_sync(0xFFFFFFFFu, part[i], 2);
    }
    if (q == 0) {
        int rbase = b * S_ + s_base + warp_m * 32 + grp;
        atomicAdd(&g_scores[rbase],      part[0]);
        atomicAdd(&g_scores[rbase + 8],  part[1]);
        atomicAdd(&g_scores[rbase + 16], part[2]);
        atomicAdd(&g_scores[rbase + 24], part[3]);
    }
}

// ---------------------------------------------------------------------------
// Softmax over S per batch (masked)
// ---------------------------------------------------------------------------
__global__ __launch_bounds__(256) void softmax_kernel(
    const int* __restrict__ src_mask,
    float* __restrict__ attn_out)
{
    __shared__ float red[8];
    int b = blockIdx.x, tid = threadIdx.x;
    int lane = tid & 31, wid = tid >> 5;

    float v[8];
    float mx = -3.4e38f;
    #pragma unroll
    for (int j = 0; j < 8; j++) {
        int idx = tid + j * 256;
        float s = g_scores[b * S_ + idx];
        if (src_mask[b * S_ + idx] == 0) s = -3.4e38f;
        v[j] = s;
        mx = fmaxf(mx, s);
    }
    #pragma unroll
    for (int off = 16; off > 0; off >>= 1)
        mx = fmaxf(mx, __shfl_xor_sync(0xFFFFFFFFu, mx, off));
    if (lane == 0) red[wid] = mx;
    __syncthreads();
    if (tid == 0) {
        float m2 = red[0];
        #pragma unroll
        for (int w = 1; w < 8; w++) m2 = fmaxf(m2, red[w]);
        red[0] = m2;
    }
    __syncthreads();
    mx = red[0];
    __syncthreads();

    float e[8];
    float sum = 0.0f;
    #pragma unroll
    for (int j = 0; j < 8; j++) {
        e[j] = __expf(v[j] - mx);
        sum += e[j];
    }
    #pragma unroll
    for (int off = 16; off > 0; off >>= 1)
        sum += __shfl_xor_sync(0xFFFFFFFFu, sum, off);
    if (lane == 0) red[wid] = sum;
    __syncthreads();
    if (tid == 0) {
        float s2 = 0.0f;
        #pragma unroll
        for (int w = 0; w < 8; w++) s2 += red[w];
        red[0] = s2;
    }
    __syncthreads();
    float inv = 1.0f / red[0];

    #pragma unroll
    for (int j = 0; j < 8; j++)
        attn_out[b * S_ + tid + j * 256] = e[j] * inv;
}

// ---------------------------------------------------------------------------
// context[b][m] += sum_{s in chunk} attn[b][s] * mem[b][s][m]
// grid (4 m-chunks, 4 s-chunks, 64 b) = 1024 CTAs; atomicAdd partials.
// ---------------------------------------------------------------------------
#define SCHUNK 512
__global__ __launch_bounds__(256) void context_kernel(
    const float* __restrict__ attn,
    const float* __restrict__ memory_bank,
    float* __restrict__ ctx_out)
{
    __shared__ float sa[SCHUNK];
    int tid = threadIdx.x;
    int b   = blockIdx.z;
    int s0  = blockIdx.y * SCHUNK;
    int m0  = blockIdx.x * 256;

    #pragma unroll
    for (int j = 0; j < SCHUNK / 256; j++)
        sa[tid + j * 256] = attn[b * S_ + s0 + tid + j * 256];
    __syncthreads();

    const float* base = memory_bank + ((size_t)b * S_ + s0) * M_ + m0 + tid;
    float a0 = 0.f, a1 = 0.f, a2 = 0.f, a3 = 0.f;
    for (int s = 0; s < SCHUNK; s += 4) {
        a0 += sa[s + 0] * base[(size_t)(s + 0) * M_];
        a1 += sa[s + 1] * base[(size_t)(s + 1) * M_];
        a2 += sa[s + 2] * base[(size_t)(s + 2) * M_];
        a3 += sa[s + 3] * base[(size_t)(s + 3) * M_];
    }
    atomicAdd(&ctx_out[b * M_ + m0 + tid], (a0 + a1) + (a2 + a3));
}

// ---------------------------------------------------------------------------
// Launch
// ---------------------------------------------------------------------------
extern "C" void kernel_launch(void* const* d_in, const int* in_sizes, int n_in,
                              void* d_out, int out_size)
{
    const float* decoder_state = (const float*)d_in[0];
    const float* memory_bank   = (const float*)d_in[1];
    const int*   src_mask      = (const int*)  d_in[2];
    const float* W_v           = (const float*)d_in[3];
    const float* W_dec         = (const float*)d_in[4];
    const float* W_mem         = (const float*)d_in[5];

    float* out  = (float*)d_out;
    float* ctx  = out;                 // [64, 1024]
    float* attn = out + B_ * M_;       // [64, 2048]

    cudaFuncSetAttribute(scores_mma_kernel,
                         cudaFuncAttributeMaxDynamicSharedMemorySize, SM_BYTES);

    zero_kernel<<<B_ * S_ / 512, 512>>>(ctx);
    transpose_kernel<<<dim3(32, 32), 256>>>(W_mem);
    dec_feat_kernel<<<dim3(D_ / 256, B_ / 4), 256>>>(decoder_state, W_dec);
    scores_mma_kernel<<<dim3(D_ / 128, S_ / 128, B_), 256, SM_BYTES>>>(memory_bank, W_v);
    softmax_kernel<<<B_, 256>>>(src_mask, attn);
    context_kernel<<<dim3(M_ / 256, S_ / SCHUNK, B_), 256>>>(attn, memory_bank, ctx);
}

// round 8
// speedup vs baseline: 1.1195x; 1.0116x over previous
#include <cuda_runtime.h>
#include <cuda_bf16.h>
#include <cstdint>
#include <math.h>

// Problem sizes (fixed)
#define B_   64
#define S_   2048
#define M_   1024   // K of scores GEMM (memory feature dim)
#define D_   1024   // N of scores GEMM (decoder feature dim)

// ---------------------------------------------------------------------------
// Scratch (no allocations allowed)
// ---------------------------------------------------------------------------
__device__ float g_scores[B_ * S_];          // 512 KB
__device__ float g_decf[B_ * D_];            // 256 KB
__device__ float g_Wt[D_ * M_];              // 4 MB: W_mem transposed [d][k'], K pair-permuted

// ---------------------------------------------------------------------------
// Helpers
// ---------------------------------------------------------------------------
__device__ __forceinline__ uint32_t smem_u32(const void* p) {
    uint32_t a;
    asm("{ .reg .u64 t; cvta.to.shared.u64 t, %1; cvt.u32.u64 %0, t; }"
        : "=r"(a) : "l"(p));
    return a;
}

__device__ __forceinline__ void cp_async16(uint32_t dst, const void* src) {
    asm volatile("cp.async.cg.shared.global [%0], [%1], 16;"
                 :: "r"(dst), "l"(src));
}
#define CP_ASYNC_COMMIT() asm volatile("cp.async.commit_group;" ::: "memory")
#define CP_ASYNC_WAIT(n)  asm volatile("cp.async.wait_group %0;" :: "n"(n) : "memory")

// mma.sync m16n8k8 tf32 (legacy tensor path, valid on compute_103)
__device__ __forceinline__ void mma_tf32(float* c,
                                         float a0, float a1, float a2, float a3,
                                         float b0, float b1) {
    asm volatile(
        "mma.sync.aligned.m16n8k8.row.col.f32.tf32.tf32.f32 "
        "{%0,%1,%2,%3}, {%4,%5,%6,%7}, {%8,%9}, {%0,%1,%2,%3};"
        : "+f"(c[0]), "+f"(c[1]), "+f"(c[2]), "+f"(c[3])
        : "r"(__float_as_uint(a0)), "r"(__float_as_uint(a1)),
          "r"(__float_as_uint(a2)), "r"(__float_as_uint(a3)),
          "r"(__float_as_uint(b0)), "r"(__float_as_uint(b1)));
}

// ---------------------------------------------------------------------------
// Prep kernel: one launch doing three independent jobs, split by blockIdx.x
//   [0, 1024)        : transpose W_mem -> g_Wt (with K pair-permutation)
//   [1024, 1088)     : dec_feat = decoder_state @ W_dec
//   [1088, 1856)     : zero g_scores and ctx
// ---------------------------------------------------------------------------
#define PREP_T0   0
#define PREP_D0   1024
#define PREP_Z0   1088
#define PREP_NB   1856

__global__ __launch_bounds__(256) void prep_kernel(
    const float* __restrict__ W,               // W_mem [k][d]
    const float* __restrict__ decoder_state,
    const float* __restrict__ W_dec,
    float* __restrict__ ctx)
{
    __shared__ float shmem[4 * M_];            // 16 KB, used by two branches
    int bid = blockIdx.x;
    int tid = threadIdx.x;

    if (bid < PREP_D0) {
        // ---- transpose + K pair-permutation:  p(k)=(k&~7)|((k&3)<<1)|((k>>2)&1)
        float (*t)[33] = reinterpret_cast<float (*)[33]>(shmem);
        int dblk = (bid & 31) * 32;
        int kblk = (bid >> 5) * 32;
        int tx = tid & 31;
        int ty = tid >> 5;     // 0..7
        #pragma unroll
        for (int j = 0; j < 32; j += 8)
            t[ty + j][tx] = W[(size_t)(kblk + ty + j) * D_ + dblk + tx];
        __syncthreads();
        int kp = (tx & ~7) | ((tx & 3) << 1) | ((tx >> 2) & 1);
        #pragma unroll
        for (int j = 0; j < 32; j += 8)
            g_Wt[(size_t)(dblk + ty + j) * M_ + kblk + kp] = t[tx][ty + j];
    } else if (bid < PREP_Z0) {
        // ---- dec_feat: 64 blocks, block idx -> (d-chunk 0..3, batch-group 0..15)
        int idx = bid - PREP_D0;
        int d   = (idx & 3) * 256 + tid;
        int bg  = (idx >> 2) * 4;
        for (int i = tid; i < 4 * M_; i += 256)
            shmem[i] = decoder_state[(bg + (i >> 10)) * M_ + (i & (M_ - 1))];
        __syncthreads();
        float a0 = 0.f, a1 = 0.f, a2 = 0.f, a3 = 0.f;
        for (int m = 0; m < M_; m++) {
            float w = W_dec[(size_t)m * D_ + d];
            a0 += shmem[m] * w;
            a1 += shmem[M_ + m] * w;
            a2 += shmem[2 * M_ + m] * w;
            a3 += shmem[3 * M_ + m] * w;
        }
        g_decf[(bg + 0) * D_ + d] = a0;
        g_decf[(bg + 1) * D_ + d] = a1;
        g_decf[(bg + 2) * D_ + d] = a2;
        g_decf[(bg + 3) * D_ + d] = a3;
    } else {
        // ---- zero scores (131072) then ctx (65536): 768 blocks x 256
        int i = (bid - PREP_Z0) * 256 + tid;
        if (i < B_ * S_) g_scores[i] = 0.0f;
        else             ctx[i - B_ * S_] = 0.0f;
    }
}

// ---------------------------------------------------------------------------
// Scores GEMM: C[s][d] = sum_k mem[b][s][k] * W_mem[k][d], fused
//   score[s] += sum_d Wv[d] * tanh(C[s][d] + decf[b][d])
// (R5/R7 configuration — measured best: 1341 us, tensor 67.4%)
// ---------------------------------------------------------------------------
#define A_FLOATS (128 * 32)
#define B_STRIDE 40
#define STAGE_FLOATS (A_FLOATS + 128 * B_STRIDE)    // 9216 floats (36864 B)
#define STAGES 3
#define SM_BYTES (STAGES * STAGE_FLOATS * 4)        // 110592

extern __shared__ float smem[];

__global__ __launch_bounds__(256, 2)
void scores_mma_kernel(const float* __restrict__ memory_bank,
                       const float* __restrict__ W_v)
{
    int tid  = threadIdx.x;
    int wid  = tid >> 5;
    int lane = tid & 31;
    int grp  = lane >> 2;         // 0..7
    int q    = lane & 3;          // 0..3
    int warp_m = wid & 3;         // 4 warps along s
    int warp_n = wid >> 2;        // 2 warps along d

    int d_base = blockIdx.x * 128;     // d fastest-varying -> A reuse in L2
    int s_base = blockIdx.y * 128;
    int b      = blockIdx.z;

    const float* Abase = memory_bank + ((size_t)b * S_ + s_base) * M_;
    const float* Bbase = g_Wt + (size_t)d_base * M_;

    uint32_t smem_base = smem_u32(smem);

    int lrow = tid >> 3;          // 0..31 (combined with +32*i)
    int lc   = tid & 7;           // 16B chunk within row
    int lcA  = lc ^ (lrow & 7);   // XOR-swizzled A chunk

    auto load_stage = [&](int kt, int st) {
        int k0 = kt * 32;
        uint32_t dstA = smem_base + (uint32_t)(st * STAGE_FLOATS) * 4;
        uint32_t dstB = dstA + A_FLOATS * 4;
        #pragma unroll
        for (int i = 0; i < 4; i++) {
            int row = lrow + i * 32;
            cp_async16(dstA + (uint32_t)(row * 32 + lcA * 4) * 4,
                       Abase + (size_t)row * M_ + k0 + lc * 4);
        }
        #pragma unroll
        for (int i = 0; i < 4; i++) {
            int row = lrow + i * 32;
            cp_async16(dstB + (uint32_t)(row * B_STRIDE + lc * 4) * 4,
                       Bbase + (size_t)row * M_ + k0 + lc * 4);
        }
        CP_ASYNC_COMMIT();
    };

    float acc[2][8][4];
    #pragma unroll
    for (int mt = 0; mt < 2; mt++)
        #pragma unroll
        for (int nt = 0; nt < 8; nt++)
            #pragma unroll
            for (int i = 0; i < 4; i++)
                acc[mt][nt][i] = 0.0f;

    load_stage(0, 0);
    load_stage(1, 1);

    int rowA0 = warp_m * 32 + grp;
    int rowB0 = warp_n * 64 + grp;

    for (int kt = 0; kt < 32; kt++) {
        if (kt == 31) { CP_ASYNC_WAIT(0); } else { CP_ASYNC_WAIT(1); }
        __syncthreads();

        if (kt + 2 < 32) load_stage(kt + 2, (kt + 2) % 3);

        const float* stA = smem + (kt % 3) * STAGE_FLOATS;
        const float* stB = stA + A_FLOATS;
        const float* bb  = stB + (size_t)rowB0 * B_STRIDE + 2 * q;

        #pragma unroll
        for (int ks = 0; ks < 4; ks++) {
            float2 bf[8];
            #pragma unroll
            for (int nt = 0; nt < 8; nt++)
                bf[nt] = *reinterpret_cast<const float2*>(
                    bb + nt * 8 * B_STRIDE + ks * 8);

            int c0 = ((2 * ks) ^ grp) * 4 + q;       // k = ks*8+q   (swizzled)
            int c1 = ((2 * ks + 1) ^ grp) * 4 + q;   // k = ks*8+q+4 (swizzled)
            #pragma unroll
            for (int mt = 0; mt < 2; mt++) {
                int r0 = rowA0 + mt * 16;
                float a0 = stA[r0 * 32 + c0];
                float a1 = stA[(r0 + 8) * 32 + c0];
                float a2 = stA[r0 * 32 + c1];
                float a3 = stA[(r0 + 8) * 32 + c1];
                #pragma unroll
                for (int nt = 0; nt < 8; nt++)
                    mma_tf32(acc[mt][nt], a0, a1, a2, a3, bf[nt].x, bf[nt].y);
            }
        }
    }

    // ---- epilogue: score[s] += sum_d Wv[d]*tanh(C + decf[d]) ----
    __syncthreads();
    float* s_df = smem;           // [128]
    float* s_wv = smem + 128;     // [128]
    if (tid < 128)       s_df[tid] = g_decf[b * D_ + d_base + tid];
    else                 s_wv[tid - 128] = W_v[d_base + tid - 128];
    __syncthreads();

    float part[4] = {0.f, 0.f, 0.f, 0.f};
    #pragma unroll
    for (int mt = 0; mt < 2; mt++) {
        #pragma unroll
        for (int nt = 0; nt < 8; nt++) {
            int col0 = warp_n * 64 + nt * 8 + 2 * q;
            float wv0 = s_wv[col0], wv1 = s_wv[col0 + 1];
            float df0 = s_df[col0], df1 = s_df[col0 + 1];
            part[2 * mt]     += wv0 * tanhf(acc[mt][nt][0] + df0)
                              + wv1 * tanhf(acc[mt][nt][1] + df1);
            part[2 * mt + 1] += wv0 * tanhf(acc[mt][nt][2] + df0)
                              + wv1 * tanhf(acc[mt][nt][3] + df1);
        }
    }
    #pragma unroll
    for (int i = 0; i < 4; i++) {
        part[i] += __shfl_xor_sync(0xFFFFFFFFu, part[i], 1);
        part[i] += __shfl_xor_sync(0xFFFFFFFFu, part[i], 2);
    }
    if (q == 0) {
        int rbase = b * S_ + s_base + warp_m * 32 + grp;
        atomicAdd(&g_scores[rbase],      part[0]);
        atomicAdd(&g_scores[rbase + 8],  part[1]);
        atomicAdd(&g_scores[rbase + 16], part[2]);
        atomicAdd(&g_scores[rbase + 24], part[3]);
    }
}

// ---------------------------------------------------------------------------
// Fused masked softmax + context.
// grid (8 s-chunks of 256, 64 b), block 256.
// Each CTA recomputes the (cheap, deterministic) softmax stats over all S,
// writes attn for its own 256-wide s-chunk, then accumulates its context
// partial with float4 loads and atomicAdd into ctx.
// ---------------------------------------------------------------------------
#define CCHUNK 256

__global__ __launch_bounds__(256) void softmax_context_kernel(
    const int* __restrict__ src_mask,
    const float* __restrict__ memory_bank,
    float* __restrict__ attn_out,
    float* __restrict__ ctx_out)
{
    __shared__ float red[8];
    __shared__ float sa[CCHUNK];
    int tid = threadIdx.x;
    int lane = tid & 31, wid = tid >> 5;
    int b  = blockIdx.y;
    int s0 = blockIdx.x * CCHUNK;

    // ---- softmax stats over the whole row (identical in all 8 CTAs of b) ----
    float v[8];
    float mx = -3.4e38f;
    #pragma unroll
    for (int j = 0; j < 8; j++) {
        int idx = tid + j * 256;
        float s = g_scores[b * S_ + idx];
        if (src_mask[b * S_ + idx] == 0) s = -3.4e38f;
        v[j] = s;
        mx = fmaxf(mx, s);
    }
    #pragma unroll
    for (int off = 16; off > 0; off >>= 1)
        mx = fmaxf(mx, __shfl_xor_sync(0xFFFFFFFFu, mx, off));
    if (lane == 0) red[wid] = mx;
    __syncthreads();
    if (tid == 0) {
        float m2 = red[0];
        #pragma unroll
        for (int w = 1; w < 8; w++) m2 = fmaxf(m2, red[w]);
        red[0] = m2;
    }
    __syncthreads();
    mx = red[0];
    __syncthreads();

    float sum = 0.0f;
    #pragma unroll
    for (int j = 0; j < 8; j++)
        sum += __expf(v[j] - mx);
    #pragma unroll
    for (int off = 16; off > 0; off >>= 1)
        sum += __shfl_xor_sync(0xFFFFFFFFu, sum, off);
    if (lane == 0) red[wid] = sum;
    __syncthreads();
    if (tid == 0) {
        float s2 = 0.0f;
        #pragma unroll
        for (int w = 0; w < 8; w++) s2 += red[w];
        red[0] = s2;
    }
    __syncthreads();
    float inv = 1.0f / red[0];

    // ---- this CTA's attn chunk: s = s0 + tid corresponds to v[blockIdx.x] ----
    float a = __expf(v[blockIdx.x] - mx) * inv;
    attn_out[b * S_ + s0 + tid] = a;
    sa[tid] = a;
    __syncthreads();

    // ---- context partial: ctx[b][m] += sum_{s in chunk} attn*mem, float4 ----
    const float4* base = reinterpret_cast<const float4*>(
        memory_bank + ((size_t)b * S_ + s0) * M_) + tid;   // m = 4*tid
    float4 acc0 = {0.f, 0.f, 0.f, 0.f};
    float4 acc1 = {0.f, 0.f, 0.f, 0.f};
    #pragma unroll 4
    for (int s = 0; s < CCHUNK; s += 2) {
        float w0 = sa[s], w1 = sa[s + 1];
        float4 v0 = base[(size_t)s * (M_ / 4)];
        float4 v1 = base[(size_t)(s + 1) * (M_ / 4)];
        acc0.x += w0 * v0.x; acc0.y += w0 * v0.y;
        acc0.z += w0 * v0.z; acc0.w += w0 * v0.w;
        acc1.x += w1 * v1.x; acc1.y += w1 * v1.y;
        acc1.z += w1 * v1.z; acc1.w += w1 * v1.w;
    }
    float* dst = ctx_out + b * M_ + tid * 4;
    atomicAdd(dst + 0, acc0.x + acc1.x);
    atomicAdd(dst + 1, acc0.y + acc1.y);
    atomicAdd(dst + 2, acc0.z + acc1.z);
    atomicAdd(dst + 3, acc0.w + acc1.w);
}

// ---------------------------------------------------------------------------
// Launch
// ---------------------------------------------------------------------------
extern "C" void kernel_launch(void* const* d_in, const int* in_sizes, int n_in,
                              void* d_out, int out_size)
{
    const float* decoder_state = (const float*)d_in[0];
    const float* memory_bank   = (const float*)d_in[1];
    const int*   src_mask      = (const int*)  d_in[2];
    const float* W_v           = (const float*)d_in[3];
    const float* W_dec         = (const float*)d_in[4];
    const float* W_mem         = (const float*)d_in[5];

    float* out  = (float*)d_out;
    float* ctx  = out;                 // [64, 1024]
    float* attn = out + B_ * M_;       // [64, 2048]

    cudaFuncSetAttribute(scores_mma_kernel,
                         cudaFuncAttributeMaxDynamicSharedMemorySize, SM_BYTES);

    prep_kernel<<<PREP_NB, 256>>>(W_mem, decoder_state, W_dec, ctx);
    scores_mma_kernel<<<dim3(D_ / 128, S_ / 128, B_), 256, SM_BYTES>>>(memory_bank, W_v);
    softmax_context_kernel<<<dim3(S_ / CCHUNK, B_), 256>>>(src_mask, memory_bank, attn, ctx);
}

// round 9
// speedup vs baseline: 1.1944x; 1.0669x over previous
#include <cuda_runtime.h>
#include <cuda_bf16.h>
#include <cstdint>
#include <math.h>

// Problem sizes (fixed)
#define B_   64
#define S_   2048
#define M_   1024   // K of scores GEMM (memory feature dim)
#define D_   1024   // N of scores GEMM (decoder feature dim)

// ---------------------------------------------------------------------------
// Scratch (no allocations allowed)
// ---------------------------------------------------------------------------
__device__ float g_scores[B_ * S_];          // 512 KB
__device__ float g_decf8[8][B_ * D_];        // 2 MB: dec_feat partials (8 K-chunks)
__device__ float g_Wt[D_ * M_];              // 4 MB: W_mem transposed [d][k'], K pair-permuted

// ---------------------------------------------------------------------------
// Helpers
// ---------------------------------------------------------------------------
__device__ __forceinline__ uint32_t smem_u32(const void* p) {
    uint32_t a;
    asm("{ .reg .u64 t; cvta.to.shared.u64 t, %1; cvt.u32.u64 %0, t; }"
        : "=r"(a) : "l"(p));
    return a;
}

__device__ __forceinline__ void cp_async16(uint32_t dst, const void* src) {
    asm volatile("cp.async.cg.shared.global [%0], [%1], 16;"
                 :: "r"(dst), "l"(src));
}
#define CP_ASYNC_COMMIT() asm volatile("cp.async.commit_group;" ::: "memory")
#define CP_ASYNC_WAIT(n)  asm volatile("cp.async.wait_group %0;" :: "n"(n) : "memory")

// mma.sync m16n8k8 tf32 (legacy tensor path, valid on compute_103)
__device__ __forceinline__ void mma_tf32(float* c,
                                         float a0, float a1, float a2, float a3,
                                         float b0, float b1) {
    asm volatile(
        "mma.sync.aligned.m16n8k8.row.col.f32.tf32.tf32.f32 "
        "{%0,%1,%2,%3}, {%4,%5,%6,%7}, {%8,%9}, {%0,%1,%2,%3};"
        : "+f"(c[0]), "+f"(c[1]), "+f"(c[2]), "+f"(c[3])
        : "r"(__float_as_uint(a0)), "r"(__float_as_uint(a1)),
          "r"(__float_as_uint(a2)), "r"(__float_as_uint(a3)),
          "r"(__float_as_uint(b0)), "r"(__float_as_uint(b1)));
}

// ---------------------------------------------------------------------------
// Prep kernel: one launch, three independent jobs, split by blockIdx.x
//   [0, 1024)        : transpose W_mem -> g_Wt (with K pair-permutation)
//   [1024, 1536)     : dec_feat partials: 4 d-chunks x 16 bgroups x 8 m-chunks
//   [1536, 2304)     : zero g_scores and ctx
// ---------------------------------------------------------------------------
#define PREP_T0   0
#define PREP_D0   1024
#define PREP_Z0   1536
#define PREP_NB   2304

__global__ __launch_bounds__(256) void prep_kernel(
    const float* __restrict__ W,               // W_mem [k][d]
    const float* __restrict__ decoder_state,
    const float* __restrict__ W_dec,
    float* __restrict__ ctx)
{
    __shared__ float shmem[32 * 33 + 32];      // transpose tile / ds chunk
    int bid = blockIdx.x;
    int tid = threadIdx.x;

    if (bid < PREP_D0) {
        // ---- transpose + K pair-permutation:  p(k)=(k&~7)|((k&3)<<1)|((k>>2)&1)
        float (*t)[33] = reinterpret_cast<float (*)[33]>(shmem);
        int dblk = (bid & 31) * 32;
        int kblk = (bid >> 5) * 32;
        int tx = tid & 31;
        int ty = tid >> 5;     // 0..7
        #pragma unroll
        for (int j = 0; j < 32; j += 8)
            t[ty + j][tx] = W[(size_t)(kblk + ty + j) * D_ + dblk + tx];
        __syncthreads();
        int kp = (tx & ~7) | ((tx & 3) << 1) | ((tx >> 2) & 1);
        #pragma unroll
        for (int j = 0; j < 32; j += 8)
            g_Wt[(size_t)(dblk + ty + j) * M_ + kblk + kp] = t[tx][ty + j];
    } else if (bid < PREP_Z0) {
        // ---- dec_feat partial over one 128-wide m-chunk ----
        int idx = bid - PREP_D0;               // 0..511
        int dch = idx & 3;                     // d-chunk (256 d)
        int bg  = ((idx >> 2) & 15) * 4;       // batch group (4 batches)
        int mc  = idx >> 6;                    // m-chunk 0..7
        int m0  = mc * 128;
        int d   = dch * 256 + tid;

        float* ds = shmem;                     // [4][128]
        for (int i = tid; i < 4 * 128; i += 256)
            ds[i] = decoder_state[(bg + (i >> 7)) * M_ + m0 + (i & 127)];
        __syncthreads();

        float a0 = 0.f, a1 = 0.f, a2 = 0.f, a3 = 0.f;
        #pragma unroll 4
        for (int m = 0; m < 128; m++) {
            float w = W_dec[(size_t)(m0 + m) * D_ + d];
            a0 += ds[m] * w;
            a1 += ds[128 + m] * w;
            a2 += ds[256 + m] * w;
            a3 += ds[384 + m] * w;
        }
        g_decf8[mc][(bg + 0) * D_ + d] = a0;
        g_decf8[mc][(bg + 1) * D_ + d] = a1;
        g_decf8[mc][(bg + 2) * D_ + d] = a2;
        g_decf8[mc][(bg + 3) * D_ + d] = a3;
    } else {
        // ---- zero scores (131072) then ctx (65536): 768 blocks x 256
        int i = (bid - PREP_Z0) * 256 + tid;
        if (i < B_ * S_) g_scores[i] = 0.0f;
        else             ctx[i - B_ * S_] = 0.0f;
    }
}

// ---------------------------------------------------------------------------
// Scores GEMM: C[s][d] = sum_k mem[b][s][k] * W_mem[k][d], fused
//   score[s] += sum_d Wv[d] * tanh(C[s][d] + decf[b][d])
// (R5/R7 configuration — measured best: 1341 us, tensor 67.4%)
// ---------------------------------------------------------------------------
#define A_FLOATS (128 * 32)
#define B_STRIDE 40
#define STAGE_FLOATS (A_FLOATS + 128 * B_STRIDE)    // 9216 floats (36864 B)
#define STAGES 3
#define SM_BYTES (STAGES * STAGE_FLOATS * 4)        // 110592

extern __shared__ float smem[];

__global__ __launch_bounds__(256, 2)
void scores_mma_kernel(const float* __restrict__ memory_bank,
                       const float* __restrict__ W_v)
{
    int tid  = threadIdx.x;
    int wid  = tid >> 5;
    int lane = tid & 31;
    int grp  = lane >> 2;         // 0..7
    int q    = lane & 3;          // 0..3
    int warp_m = wid & 3;         // 4 warps along s
    int warp_n = wid >> 2;        // 2 warps along d

    int d_base = blockIdx.x * 128;     // d fastest-varying -> A reuse in L2
    int s_base = blockIdx.y * 128;
    int b      = blockIdx.z;

    const float* Abase = memory_bank + ((size_t)b * S_ + s_base) * M_;
    const float* Bbase = g_Wt + (size_t)d_base * M_;

    uint32_t smem_base = smem_u32(smem);

    int lrow = tid >> 3;          // 0..31 (combined with +32*i)
    int lc   = tid & 7;           // 16B chunk within row
    int lcA  = lc ^ (lrow & 7);   // XOR-swizzled A chunk

    auto load_stage = [&](int kt, int st) {
        int k0 = kt * 32;
        uint32_t dstA = smem_base + (uint32_t)(st * STAGE_FLOATS) * 4;
        uint32_t dstB = dstA + A_FLOATS * 4;
        #pragma unroll
        for (int i = 0; i < 4; i++) {
            int row = lrow + i * 32;
            cp_async16(dstA + (uint32_t)(row * 32 + lcA * 4) * 4,
                       Abase + (size_t)row * M_ + k0 + lc * 4);
        }
        #pragma unroll
        for (int i = 0; i < 4; i++) {
            int row = lrow + i * 32;
            cp_async16(dstB + (uint32_t)(row * B_STRIDE + lc * 4) * 4,
                       Bbase + (size_t)row * M_ + k0 + lc * 4);
        }
        CP_ASYNC_COMMIT();
    };

    float acc[2][8][4];
    #pragma unroll
    for (int mt = 0; mt < 2; mt++)
        #pragma unroll
        for (int nt = 0; nt < 8; nt++)
            #pragma unroll
            for (int i = 0; i < 4; i++)
                acc[mt][nt][i] = 0.0f;

    load_stage(0, 0);
    load_stage(1, 1);

    int rowA0 = warp_m * 32 + grp;
    int rowB0 = warp_n * 64 + grp;

    for (int kt = 0; kt < 32; kt++) {
        if (kt == 31) { CP_ASYNC_WAIT(0); } else { CP_ASYNC_WAIT(1); }
        __syncthreads();

        if (kt + 2 < 32) load_stage(kt + 2, (kt + 2) % 3);

        const float* stA = smem + (kt % 3) * STAGE_FLOATS;
        const float* stB = stA + A_FLOATS;
        const float* bb  = stB + (size_t)rowB0 * B_STRIDE + 2 * q;

        #pragma unroll
        for (int ks = 0; ks < 4; ks++) {
            float2 bf[8];
            #pragma unroll
            for (int nt = 0; nt < 8; nt++)
                bf[nt] = *reinterpret_cast<const float2*>(
                    bb + nt * 8 * B_STRIDE + ks * 8);

            int c0 = ((2 * ks) ^ grp) * 4 + q;       // k = ks*8+q   (swizzled)
            int c1 = ((2 * ks + 1) ^ grp) * 4 + q;   // k = ks*8+q+4 (swizzled)
            #pragma unroll
            for (int mt = 0; mt < 2; mt++) {
                int r0 = rowA0 + mt * 16;
                float a0 = stA[r0 * 32 + c0];
                float a1 = stA[(r0 + 8) * 32 + c0];
                float a2 = stA[r0 * 32 + c1];
                float a3 = stA[(r0 + 8) * 32 + c1];
                #pragma unroll
                for (int nt = 0; nt < 8; nt++)
                    mma_tf32(acc[mt][nt], a0, a1, a2, a3, bf[nt].x, bf[nt].y);
            }
        }
    }

    // ---- epilogue: score[s] += sum_d Wv[d]*tanh(C + decf[d]) ----
    __syncthreads();
    float* s_df = smem;           // [128]
    float* s_wv = smem + 128;     // [128]
    if (tid < 128) {
        int gi = b * D_ + d_base + tid;
        float df = g_decf8[0][gi];
        #pragma unroll
        for (int c = 1; c < 8; c++) df += g_decf8[c][gi];
        s_df[tid] = df;
    } else {
        s_wv[tid - 128] = W_v[d_base + tid - 128];
    }
    __syncthreads();

    float part[4] = {0.f, 0.f, 0.f, 0.f};
    #pragma unroll
    for (int mt = 0; mt < 2; mt++) {
        #pragma unroll
        for (int nt = 0; nt < 8; nt++) {
            int col0 = warp_n * 64 + nt * 8 + 2 * q;
            float wv0 = s_wv[col0], wv1 = s_wv[col0 + 1];
            float df0 = s_df[col0], df1 = s_df[col0 + 1];
            part[2 * mt]     += wv0 * tanhf(acc[mt][nt][0] + df0)
                              + wv1 * tanhf(acc[mt][nt][1] + df1);
            part[2 * mt + 1] += wv0 * tanhf(acc[mt][nt][2] + df0)
                              + wv1 * tanhf(acc[mt][nt][3] + df1);
        }
    }
    #pragma unroll
    for (int i = 0; i < 4; i++) {
        part[i] += __shfl_xor_sync(0xFFFFFFFFu, part[i], 1);
        part[i] += __shfl_xor_sync(0xFFFFFFFFu, part[i], 2);
    }
    if (q == 0) {
        int rbase = b * S_ + s_base + warp_m * 32 + grp;
        atomicAdd(&g_scores[rbase],      part[0]);
        atomicAdd(&g_scores[rbase + 8],  part[1]);
        atomicAdd(&g_scores[rbase + 16], part[2]);
        atomicAdd(&g_scores[rbase + 24], part[3]);
    }
}

// ---------------------------------------------------------------------------
// Fused masked softmax + context.
// grid (8 s-chunks of 256, 64 b), block 256.
// ---------------------------------------------------------------------------
#define CCHUNK 256

__global__ __launch_bounds__(256) void softmax_context_kernel(
    const int* __restrict__ src_mask,
    const float* __restrict__ memory_bank,
    float* __restrict__ attn_out,
    float* __restrict__ ctx_out)
{
    __shared__ float red[8];
    __shared__ float sa[CCHUNK];
    int tid = threadIdx.x;
    int lane = tid & 31, wid = tid >> 5;
    int b  = blockIdx.y;
    int s0 = blockIdx.x * CCHUNK;

    // ---- softmax stats over the whole row (identical in all 8 CTAs of b) ----
    float v[8];
    float mx = -3.4e38f;
    #pragma unroll
    for (int j = 0; j < 8; j++) {
        int idx = tid + j * 256;
        float s = g_scores[b * S_ + idx];
        if (src_mask[b * S_ + idx] == 0) s = -3.4e38f;
        v[j] = s;
        mx = fmaxf(mx, s);
    }
    #pragma unroll
    for (int off = 16; off > 0; off >>= 1)
        mx = fmaxf(mx, __shfl_xor_sync(0xFFFFFFFFu, mx, off));
    if (lane == 0) red[wid] = mx;
    __syncthreads();
    if (tid == 0) {
        float m2 = red[0];
        #pragma unroll
        for (int w = 1; w < 8; w++) m2 = fmaxf(m2, red[w]);
        red[0] = m2;
    }
    __syncthreads();
    mx = red[0];
    __syncthreads();

    float sum = 0.0f;
    #pragma unroll
    for (int j = 0; j < 8; j++)
        sum += __expf(v[j] - mx);
    #pragma unroll
    for (int off = 16; off > 0; off >>= 1)
        sum += __shfl_xor_sync(0xFFFFFFFFu, sum, off);
    if (lane == 0) red[wid] = sum;
    __syncthreads();
    if (tid == 0) {
        float s2 = 0.0f;
        #pragma unroll
        for (int w = 0; w < 8; w++) s2 += red[w];
        red[0] = s2;
    }
    __syncthreads();
    float inv = 1.0f / red[0];

    // ---- this CTA's attn chunk: s = s0 + tid corresponds to v[blockIdx.x] ----
    float a = __expf(v[blockIdx.x] - mx) * inv;
    attn_out[b * S_ + s0 + tid] = a;
    sa[tid] = a;
    __syncthreads();

    // ---- context partial: ctx[b][m] += sum_{s in chunk} attn*mem, float4 ----
    const float4* base = reinterpret_cast<const float4*>(
        memory_bank + ((size_t)b * S_ + s0) * M_) + tid;   // m = 4*tid
    float4 acc0 = {0.f, 0.f, 0.f, 0.f};
    float4 acc1 = {0.f, 0.f, 0.f, 0.f};
    #pragma unroll 4
    for (int s = 0; s < CCHUNK; s += 2) {
        float w0 = sa[s], w1 = sa[s + 1];
        float4 v0 = base[(size_t)s * (M_ / 4)];
        float4 v1 = base[(size_t)(s + 1) * (M_ / 4)];
        acc0.x += w0 * v0.x; acc0.y += w0 * v0.y;
        acc0.z += w0 * v0.z; acc0.w += w0 * v0.w;
        acc1.x += w1 * v1.x; acc1.y += w1 * v1.y;
        acc1.z += w1 * v1.z; acc1.w += w1 * v1.w;
    }
    float* dst = ctx_out + b * M_ + tid * 4;
    atomicAdd(dst + 0, acc0.x + acc1.x);
    atomicAdd(dst + 1, acc0.y + acc1.y);
    atomicAdd(dst + 2, acc0.z + acc1.z);
    atomicAdd(dst + 3, acc0.w + acc1.w);
}

// ---------------------------------------------------------------------------
// Launch
// ---------------------------------------------------------------------------
extern "C" void kernel_launch(void* const* d_in, const int* in_sizes, int n_in,
                              void* d_out, int out_size)
{
    const float* decoder_state = (const float*)d_in[0];
    const float* memory_bank   = (const float*)d_in[1];
    const int*   src_mask      = (const int*)  d_in[2];
    const float* W_v           = (const float*)d_in[3];
    const float* W_dec         = (const float*)d_in[4];
    const float* W_mem         = (const float*)d_in[5];

    float* out  = (float*)d_out;
    float* ctx  = out;                 // [64, 1024]
    float* attn = out + B_ * M_;       // [64, 2048]

    cudaFuncSetAttribute(scores_mma_kernel,
                         cudaFuncAttributeMaxDynamicSharedMemorySize, SM_BYTES);

    prep_kernel<<<PREP_NB, 256>>>(W_mem, decoder_state, W_dec, ctx);
    scores_mma_kernel<<<dim3(D_ / 128, S_ / 128, B_), 256, SM_BYTES>>>(memory_bank, W_v);
    softmax_context_kernel<<<dim3(S_ / CCHUNK, B_), 256>>>(src_mask, memory_bank, attn, ctx);
}